// round 10
// baseline (speedup 1.0000x reference)
#include <cuda_runtime.h>
#include <cuda_bf16.h>
#include <cstdint>

#define KK 64
#define NN 4096
#define MTILE 128
#define KC 32                          // n-elements per chunk
#define KSPLIT 8
#define NCHUNK ((NN / KSPLIT) / KC)    // 16
#define SROW 40                        // bf16 smem row stride (80 B)
#define FROW 36                        // fp32 ring row stride in floats (144 B)
#define RING_STAGE (MTILE * FROW)      // floats per ring stage (18 KB)
#define SMEM_RING 0                    // 3 stages * 18432 B = 55296 B
#define SMEM_XBF  (3 * RING_STAGE * 4)             // 55296
#define SMEM_ZBF  (SMEM_XBF + 2 * MTILE * SROW * 2) // 55296 + 20480 = 75776
#define SMEM_TOT  (SMEM_ZBF + 2 * KK * SROW * 2)    // 75776 + 10240 = 86016

// Partial row_sums: [KSPLIT][KK][NN] fp32 = 8 MB
__device__ float g_partial[KSPLIT * KK * NN];

static __device__ __forceinline__ uint32_t smem_u32(const void* p) {
    uint32_t a;
    asm("{ .reg .u64 t; cvta.to.shared.u64 t, %1; cvt.u32.u64 %0, t; }"
        : "=r"(a) : "l"(p));
    return a;
}
static __device__ __forceinline__ uint32_t pack2(float a, float b) {
    __nv_bfloat162 h = __floats2bfloat162_rn(a, b);
    return *reinterpret_cast<uint32_t*>(&h);
}
static __device__ __forceinline__ void sts128(uint32_t a, uint32_t x, uint32_t y,
                                              uint32_t z, uint32_t w) {
    asm volatile("st.shared.v4.b32 [%0], {%1,%2,%3,%4};"
                 :: "r"(a), "r"(x), "r"(y), "r"(z), "r"(w) : "memory");
}
static __device__ __forceinline__ void lds128(uint32_t a, float& x, float& y,
                                              float& z, float& w) {
    asm volatile("ld.shared.v4.f32 {%0,%1,%2,%3}, [%4];"
                 : "=f"(x), "=f"(y), "=f"(z), "=f"(w) : "r"(a));
}
static __device__ __forceinline__ void cpasync16(uint32_t dst, const void* src) {
    asm volatile("cp.async.cg.shared.global [%0], [%1], 16;"
                 :: "r"(dst), "l"(src) : "memory");
}
static __device__ __forceinline__ void ldsm4(uint32_t addr, uint32_t& r0, uint32_t& r1,
                                             uint32_t& r2, uint32_t& r3) {
    asm volatile("ldmatrix.sync.aligned.m8n8.x4.shared.b16 {%0,%1,%2,%3}, [%4];"
                 : "=r"(r0), "=r"(r1), "=r"(r2), "=r"(r3) : "r"(addr));
}
static __device__ __forceinline__ void mma16816(float& c0, float& c1, float& c2, float& c3,
                                                uint32_t a0, uint32_t a1, uint32_t a2,
                                                uint32_t a3, uint32_t b0, uint32_t b1) {
    asm volatile("mma.sync.aligned.m16n8k16.row.col.f32.bf16.bf16.f32 "
                 "{%0,%1,%2,%3}, {%4,%5,%6,%7}, {%8,%9}, {%0,%1,%2,%3};"
                 : "+f"(c0), "+f"(c1), "+f"(c2), "+f"(c3)
                 : "r"(a0), "r"(a1), "r"(a2), "r"(a3), "r"(b0), "r"(b1));
}

// ---------------------------------------------------------------------------
// HMMA GEMM: g_partial[by][k][i] = sum_{n in split by} zs[k][n] * X[i][n]
// grid = (32, KSPLIT) = 256 CTAs, block = 256 (8 warps: 4 i-groups x 2 k-groups)
// X: 3-deep cp.async fp32 ring -> on-chip cvt -> bf16 tiles. zs: reg staging.
// ---------------------------------------------------------------------------
__global__ __launch_bounds__(256, 2)
void gemm_hmma(const float* __restrict__ zs, const float* __restrict__ X) {
    extern __shared__ __align__(128) char dsm[];
    const uint32_t base = smem_u32(dsm);
    const uint32_t ringA = base + SMEM_RING;
    const uint32_t XsA[2] = { base + SMEM_XBF, base + SMEM_XBF + MTILE * SROW * 2 };
    const uint32_t ZsA[2] = { base + SMEM_ZBF, base + SMEM_ZBF + KK * SROW * 2 };

    const int tid   = threadIdx.x;
    const int lane  = tid & 31;
    const int wid   = tid >> 5;
    const int ibase = blockIdx.x * MTILE;
    const int nbase = blockIdx.y * (NN / KSPLIT);

    // ---- X cp.async producer: 4 units/thread (row0 = tid>>3 + 32j, q = tid&7) ----
    const int xq    = tid & 7;
    const int xrow0 = tid >> 3;
    const float* xsrc = X + (size_t)(ibase + xrow0) * NN + nbase + xq * 4;
    const uint32_t xdst = xrow0 * (FROW * 4) + xq * 16;   // offset within a ring stage

    // ---- X convert: 2 pair-units/thread (r = tid>>2 + 64j, p = tid&3) ----
    const int cp  = tid & 3;
    const int cr0 = tid >> 2;
    const uint32_t clds = cr0 * (FROW * 4) + cp * 32;     // fp32 ring read offset
    const uint32_t csts = cr0 * (SROW * 2) + cp * 16;     // bf16 tile write offset

    // ---- zs producer (reg staged; L2-resident) ----
    const int zrow = tid >> 2, zqc = tid & 3;
    const float* zp = zs + (size_t)zrow * NN + nbase + zqc * 8;
    const uint32_t zsto = zrow * (SROW * 2) + zqc * 16;

    // ---- consumer (ldmatrix) address components ----
    const int wi = (wid & 3) * 32;
    const int wj = (wid >> 2) * 32;
    const uint32_t a_row = wi + (lane & 15);
    const uint32_t a_col16 = (lane >> 4);
    const uint32_t b_row = wj + ((lane >> 4) & 1) * 8 + (lane & 7);
    const uint32_t b_col16 = ((lane >> 3) & 1);

    float acc[2][4][4];
#pragma unroll
    for (int m = 0; m < 2; ++m)
#pragma unroll
        for (int n = 0; n < 4; ++n)
#pragma unroll
            for (int q = 0; q < 4; ++q) acc[m][n][q] = 0.f;

    // ---- prologue: launch cp.async for chunks 0..2; prefetch zs chunk 0 ----
#pragma unroll
    for (int s = 0; s < 3; ++s) {
        const uint32_t rb = ringA + s * (RING_STAGE * 4) + xdst;
        const float* sb = xsrc + s * KC;
#pragma unroll
        for (int j = 0; j < 4; ++j)
            cpasync16(rb + j * 32 * (FROW * 4), sb + (size_t)j * 32 * NN);
        asm volatile("cp.async.commit_group;" ::: "memory");
    }
    float4 zr[2];
    zr[0] = *(const float4*)(zp);
    zr[1] = *(const float4*)(zp + 4);

#pragma unroll 1
    for (int c = 0; c < NCHUNK; ++c) {
        const int buf = c & 1;
        const uint32_t ring = ringA + (c % 3) * (RING_STAGE * 4);

        asm volatile("cp.async.wait_group 2;" ::: "memory");
        __syncthreads();                       // chunk c fp32 visible; MMA(c-1) done

        // convert X fp32 -> bf16 tile
#pragma unroll
        for (int j = 0; j < 2; ++j) {
            float f0, f1, f2, f3, f4, f5, f6, f7;
            const uint32_t ra = ring + clds + j * 64 * (FROW * 4);
            lds128(ra,      f0, f1, f2, f3);
            lds128(ra + 16, f4, f5, f6, f7);
            sts128(XsA[buf] + csts + j * 64 * (SROW * 2),
                   pack2(f0, f1), pack2(f2, f3), pack2(f4, f5), pack2(f6, f7));
        }
        // zs staged regs -> bf16 tile
        sts128(ZsA[buf] + zsto, pack2(zr[0].x, zr[0].y), pack2(zr[0].z, zr[0].w),
                                pack2(zr[1].x, zr[1].y), pack2(zr[1].z, zr[1].w));
        __syncthreads();                       // bf16 tiles full; ring stage free

        // refill ring with chunk c+3; prefetch zs c+1
        if (c + 3 < NCHUNK) {
            const uint32_t rb = ringA + ((c + 3) % 3) * (RING_STAGE * 4) + xdst;
            const float* sb = xsrc + (c + 3) * KC;
#pragma unroll
            for (int j = 0; j < 4; ++j)
                cpasync16(rb + j * 32 * (FROW * 4), sb + (size_t)j * 32 * NN);
        }
        asm volatile("cp.async.commit_group;" ::: "memory");
        if (c + 1 < NCHUNK) {
            const int off = (c + 1) * KC;
            zr[0] = *(const float4*)(zp + off);
            zr[1] = *(const float4*)(zp + off + 4);
        }

        // 2 k16 MMA steps
#pragma unroll
        for (int s = 0; s < 2; ++s) {
            uint32_t a[2][4], b[2][4];
#pragma unroll
            for (int h = 0; h < 2; ++h)
                ldsm4(XsA[buf] + (a_row + h * 16) * (SROW * 2) + (a_col16 + s * 2) * 16,
                      a[h][0], a[h][1], a[h][2], a[h][3]);
#pragma unroll
            for (int g = 0; g < 2; ++g)
                ldsm4(ZsA[buf] + (b_row + g * 16) * (SROW * 2) + (b_col16 + s * 2) * 16,
                      b[g][0], b[g][1], b[g][2], b[g][3]);
#pragma unroll
            for (int m = 0; m < 2; ++m)
#pragma unroll
                for (int n = 0; n < 4; ++n) {
                    const int g = n >> 1, hi = (n & 1) * 2;
                    mma16816(acc[m][n][0], acc[m][n][1], acc[m][n][2], acc[m][n][3],
                             a[m][0], a[m][1], a[m][2], a[m][3],
                             b[g][hi], b[g][hi + 1]);
                }
        }
    }

    // epilogue: write warp tile to g_partial[by][j][i]
    float* part = g_partial + (size_t)blockIdx.y * (KK * NN);
#pragma unroll
    for (int m = 0; m < 2; ++m) {
        const int i0 = ibase + wi + m * 16 + (lane >> 2);
#pragma unroll
        for (int n = 0; n < 4; ++n) {
            const int j0 = wj + n * 8 + (lane & 3) * 2;
            part[(size_t)j0 * NN + i0]           = acc[m][n][0];
            part[(size_t)(j0 + 1) * NN + i0]     = acc[m][n][1];
            part[(size_t)j0 * NN + i0 + 8]       = acc[m][n][2];
            part[(size_t)(j0 + 1) * NN + i0 + 8] = acc[m][n][3];
        }
    }
}

// ---------------------------------------------------------------------------
__global__ void zero_out_kernel(float* out) { out[0] = 0.f; }

__global__ __launch_bounds__(256)
void finish_kernel(const float* __restrict__ zs, const float* __restrict__ X,
                   const float* __restrict__ vn_p, float* __restrict__ out) {
    const int idx = blockIdx.x * blockDim.x + threadIdx.x;  // covers KK*NN exactly
    const float vn = *vn_p;
    const int i = idx & (NN - 1);

    float rs = g_partial[idx];
#pragma unroll
    for (int s = 1; s < KSPLIT; ++s) rs += g_partial[idx + s * (KK * NN)];

    const float z   = zs[idx];
    const float xd  = X[(size_t)i * NN + i];
    const float num = z * xd;
    const float den = rs - num;
    float local = num / (vn + den);

#pragma unroll
    for (int off = 16; off > 0; off >>= 1)
        local += __shfl_down_sync(0xffffffffu, local, off);

    __shared__ float red[8];
    const int lane = threadIdx.x & 31;
    const int wd   = threadIdx.x >> 5;
    if (lane == 0) red[wd] = local;
    __syncthreads();
    if (wd == 0) {
        float v = (lane < 8) ? red[lane] : 0.f;
#pragma unroll
        for (int off = 4; off > 0; off >>= 1)
            v += __shfl_down_sync(0xffffffffu, v, off);
        if (lane == 0) atomicAdd(out, -v / (float)KK);
    }
}

// ---------------------------------------------------------------------------
extern "C" void kernel_launch(void* const* d_in, const int* in_sizes, int n_in,
                              void* d_out, int out_size) {
    const float* zs = (const float*)d_in[0];   // [64, 4096]
    const float* X  = (const float*)d_in[1];   // [4096, 4096]
    const float* vn = (const float*)d_in[2];   // scalar
    float* out = (float*)d_out;

    static int configured = 0;
    if (!configured) {
        cudaFuncSetAttribute(gemm_hmma, cudaFuncAttributeMaxDynamicSharedMemorySize,
                             SMEM_TOT);
        configured = 1;
    }

    dim3 grid(NN / MTILE, KSPLIT);             // 32 x 8 = 256 CTAs
    gemm_hmma<<<grid, 256, SMEM_TOT>>>(zs, X);
    zero_out_kernel<<<1, 1>>>(out);
    finish_kernel<<<(KK * NN) / 256, 256>>>(zs, X, vn, out);
}

// round 11
// speedup vs baseline: 1.1047x; 1.1047x over previous
#include <cuda_runtime.h>
#include <cuda_bf16.h>
#include <cstdint>

#define KK 64
#define NN 4096
#define MTILE 128
#define KC 32                          // n-elements per chunk
#define KSPLIT 8
#define NCHUNK ((NN / KSPLIT) / KC)    // 16 (even)
#define SROW 40                        // smem row stride in bf16 elems (80 B)

// Partial row_sums: [KSPLIT][KK][NN] fp32 = 8 MB
__device__ float g_partial[KSPLIT * KK * NN];

static __device__ __forceinline__ uint32_t smem_u32(const void* p) {
    uint32_t a;
    asm("{ .reg .u64 t; cvta.to.shared.u64 t, %1; cvt.u32.u64 %0, t; }"
        : "=r"(a) : "l"(p));
    return a;
}
static __device__ __forceinline__ uint32_t pack2(float a, float b) {
    __nv_bfloat162 h = __floats2bfloat162_rn(a, b);
    return *reinterpret_cast<uint32_t*>(&h);
}
static __device__ __forceinline__ void sts128(uint32_t a, uint32_t x, uint32_t y,
                                              uint32_t z, uint32_t w) {
    asm volatile("st.shared.v4.b32 [%0], {%1,%2,%3,%4};"
                 :: "r"(a), "r"(x), "r"(y), "r"(z), "r"(w) : "memory");
}
static __device__ __forceinline__ void ldsm4(uint32_t addr, uint32_t& r0, uint32_t& r1,
                                             uint32_t& r2, uint32_t& r3) {
    asm volatile("ldmatrix.sync.aligned.m8n8.x4.shared.b16 {%0,%1,%2,%3}, [%4];"
                 : "=r"(r0), "=r"(r1), "=r"(r2), "=r"(r3) : "r"(addr));
}
static __device__ __forceinline__ void mma16816(float& c0, float& c1, float& c2, float& c3,
                                                uint32_t a0, uint32_t a1, uint32_t a2,
                                                uint32_t a3, uint32_t b0, uint32_t b1) {
    asm volatile("mma.sync.aligned.m16n8k16.row.col.f32.bf16.bf16.f32 "
                 "{%0,%1,%2,%3}, {%4,%5,%6,%7}, {%8,%9}, {%0,%1,%2,%3};"
                 : "+f"(c0), "+f"(c1), "+f"(c2), "+f"(c3)
                 : "r"(a0), "r"(a1), "r"(a2), "r"(a3), "r"(b0), "r"(b1));
}

// ---------------------------------------------------------------------------
// HMMA GEMM: g_partial[by][k][i] = sum_{n in split by} zs[k][n] * X[i][n]
// grid = (32, KSPLIT) = 256 CTAs, block = 256 (8 warps: 4 i-groups x 2 k-groups)
// 2 CTAs/SM; register prefetch distance 2 (A/B staging sets); 1 barrier/chunk.
// ---------------------------------------------------------------------------
__global__ __launch_bounds__(256, 2)
void gemm_hmma(const float* __restrict__ zs, const float* __restrict__ X) {
    __shared__ __align__(16) __nv_bfloat16 Xs[2][MTILE * SROW];
    __shared__ __align__(16) __nv_bfloat16 Zs[2][KK * SROW];

    const int tid   = threadIdx.x;
    const int lane  = tid & 31;
    const int wid   = tid >> 5;
    const int ibase = blockIdx.x * MTILE;
    const int nbase = blockIdx.y * (NN / KSPLIT);

    const uint32_t XsA[2] = { smem_u32(Xs[0]), smem_u32(Xs[1]) };
    const uint32_t ZsA[2] = { smem_u32(Zs[0]), smem_u32(Zs[1]) };

    // ---- producer assignments (8-float units) ----
    const int xu0 = tid, xu1 = tid + 256;
    const int xrow0 = xu0 >> 2, xqc0 = xu0 & 3;
    const int xrow1 = xu1 >> 2, xqc1 = xu1 & 3;
    const float* xp0 = X + (size_t)(ibase + xrow0) * NN + nbase + xqc0 * 8;
    const float* xp1 = X + (size_t)(ibase + xrow1) * NN + nbase + xqc1 * 8;
    const uint32_t xs0 = xrow0 * (SROW * 2) + xqc0 * 16;
    const uint32_t xs1 = xrow1 * (SROW * 2) + xqc1 * 16;
    const int zrow = tid >> 2, zqc = tid & 3;
    const float* zp = zs + (size_t)zrow * NN + nbase + zqc * 8;
    const uint32_t zsto = zrow * (SROW * 2) + zqc * 16;

    // ---- consumer (ldmatrix) address components ----
    const int wi = (wid & 3) * 32;
    const int wj = (wid >> 2) * 32;
    const uint32_t a_row = wi + (lane & 15);
    const uint32_t a_col16 = (lane >> 4);
    const uint32_t b_row = wj + ((lane >> 4) & 1) * 8 + (lane & 7);
    const uint32_t b_col16 = ((lane >> 3) & 1);

    float acc[2][4][4];
#pragma unroll
    for (int m = 0; m < 2; ++m)
#pragma unroll
        for (int n = 0; n < 4; ++n)
#pragma unroll
            for (int q = 0; q < 4; ++q) acc[m][n][q] = 0.f;

#define LOAD_SET(xr, zr, off)                                              \
    do {                                                                   \
        xr[0] = *(const float4*)(xp0 + (off));                             \
        xr[1] = *(const float4*)(xp0 + (off) + 4);                         \
        xr[2] = *(const float4*)(xp1 + (off));                             \
        xr[3] = *(const float4*)(xp1 + (off) + 4);                         \
        zr[0] = *(const float4*)(zp + (off));                              \
        zr[1] = *(const float4*)(zp + (off) + 4);                          \
    } while (0)

#define STS_SET(buf, xr, zr)                                                        \
    do {                                                                            \
        sts128(XsA[buf] + xs0, pack2(xr[0].x, xr[0].y), pack2(xr[0].z, xr[0].w),    \
               pack2(xr[1].x, xr[1].y), pack2(xr[1].z, xr[1].w));                   \
        sts128(XsA[buf] + xs1, pack2(xr[2].x, xr[2].y), pack2(xr[2].z, xr[2].w),    \
               pack2(xr[3].x, xr[3].y), pack2(xr[3].z, xr[3].w));                   \
        sts128(ZsA[buf] + zsto, pack2(zr[0].x, zr[0].y), pack2(zr[0].z, zr[0].w),   \
               pack2(zr[1].x, zr[1].y), pack2(zr[1].z, zr[1].w));                   \
    } while (0)

#define MMA_PHASE(buf)                                                              \
    do {                                                                            \
        _Pragma("unroll")                                                           \
        for (int s = 0; s < 2; ++s) {                                               \
            uint32_t a[2][4], b[2][4];                                              \
            _Pragma("unroll")                                                       \
            for (int h = 0; h < 2; ++h)                                             \
                ldsm4(XsA[buf] + (a_row + h * 16) * (SROW * 2) +                    \
                          (a_col16 + s * 2) * 16,                                   \
                      a[h][0], a[h][1], a[h][2], a[h][3]);                          \
            _Pragma("unroll")                                                       \
            for (int g = 0; g < 2; ++g)                                             \
                ldsm4(ZsA[buf] + (b_row + g * 16) * (SROW * 2) +                    \
                          (b_col16 + s * 2) * 16,                                   \
                      b[g][0], b[g][1], b[g][2], b[g][3]);                          \
            _Pragma("unroll")                                                       \
            for (int m = 0; m < 2; ++m)                                             \
                _Pragma("unroll")                                                   \
                for (int n = 0; n < 4; ++n) {                                       \
                    const int g = n >> 1, hi = (n & 1) * 2;                         \
                    mma16816(acc[m][n][0], acc[m][n][1], acc[m][n][2],              \
                             acc[m][n][3], a[m][0], a[m][1], a[m][2], a[m][3],      \
                             b[g][hi], b[g][hi + 1]);                               \
                }                                                                   \
        }                                                                           \
    } while (0)

    // prologue: stage chunks 0 (set A) and 1 (set B)
    float4 xrA[4], zrA[2], xrB[4], zrB[2];
    LOAD_SET(xrA, zrA, 0);
    LOAD_SET(xrB, zrB, KC);

#pragma unroll 1
    for (int c = 0; c < NCHUNK; c += 2) {
        // even chunk c: tile buf 0, staging set A
        STS_SET(0, xrA, zrA);
        __syncthreads();
        if (c + 2 < NCHUNK) LOAD_SET(xrA, zrA, (c + 2) * KC);
        MMA_PHASE(0);

        // odd chunk c+1: tile buf 1, staging set B
        STS_SET(1, xrB, zrB);
        __syncthreads();
        if (c + 3 < NCHUNK) LOAD_SET(xrB, zrB, (c + 3) * KC);
        MMA_PHASE(1);
    }

    // epilogue: write warp tile to g_partial[by][j][i]
    float* part = g_partial + (size_t)blockIdx.y * (KK * NN);
#pragma unroll
    for (int m = 0; m < 2; ++m) {
        const int i0 = ibase + wi + m * 16 + (lane >> 2);
#pragma unroll
        for (int n = 0; n < 4; ++n) {
            const int j0 = wj + n * 8 + (lane & 3) * 2;
            part[(size_t)j0 * NN + i0]           = acc[m][n][0];
            part[(size_t)(j0 + 1) * NN + i0]     = acc[m][n][1];
            part[(size_t)j0 * NN + i0 + 8]       = acc[m][n][2];
            part[(size_t)(j0 + 1) * NN + i0 + 8] = acc[m][n][3];
        }
    }
}

// ---------------------------------------------------------------------------
__global__ void zero_out_kernel(float* out) { out[0] = 0.f; }

__global__ __launch_bounds__(256)
void finish_kernel(const float* __restrict__ zs, const float* __restrict__ X,
                   const float* __restrict__ vn_p, float* __restrict__ out) {
    const int idx = blockIdx.x * blockDim.x + threadIdx.x;  // covers KK*NN exactly
    const float vn = *vn_p;
    const int i = idx & (NN - 1);

    float rs = g_partial[idx];
#pragma unroll
    for (int s = 1; s < KSPLIT; ++s) rs += g_partial[idx + s * (KK * NN)];

    const float z   = zs[idx];
    const float xd  = X[(size_t)i * NN + i];
    const float num = z * xd;
    const float den = rs - num;
    float local = num / (vn + den);

#pragma unroll
    for (int off = 16; off > 0; off >>= 1)
        local += __shfl_down_sync(0xffffffffu, local, off);

    __shared__ float red[8];
    const int lane = threadIdx.x & 31;
    const int wd   = threadIdx.x >> 5;
    if (lane == 0) red[wd] = local;
    __syncthreads();
    if (wd == 0) {
        float v = (lane < 8) ? red[lane] : 0.f;
#pragma unroll
        for (int off = 4; off > 0; off >>= 1)
            v += __shfl_down_sync(0xffffffffu, v, off);
        if (lane == 0) atomicAdd(out, -v / (float)KK);
    }
}

// ---------------------------------------------------------------------------
extern "C" void kernel_launch(void* const* d_in, const int* in_sizes, int n_in,
                              void* d_out, int out_size) {
    const float* zs = (const float*)d_in[0];   // [64, 4096]
    const float* X  = (const float*)d_in[1];   // [4096, 4096]
    const float* vn = (const float*)d_in[2];   // scalar
    float* out = (float*)d_out;

    dim3 grid(NN / MTILE, KSPLIT);             // 32 x 8 = 256 CTAs
    gemm_hmma<<<grid, 256>>>(zs, X);
    zero_out_kernel<<<1, 1>>>(out);
    finish_kernel<<<(KK * NN) / 256, 256>>>(zs, X, vn, out);
}